// round 13
// baseline (speedup 1.0000x reference)
#include <cuda_runtime.h>

// lagrangian_ode_func_54640573940227 — FINAL
//
// out[i] = { x.z, x.w, -(k1*x0 + k2*(x0-x1)), k2*(x0-x1) }
//
// HBM-roofline streaming kernel. 256 MiB irreducible traffic at ~6.0 TB/s,
// the GB300 mixed read/write DRAM ceiling (75% of 8 TB/s spec).
// 12-round sweep: per-warp MLP 1-16 (optimum 8), occupancy 21-83%, grid
// 1024-32768 (incl. persistent single-wave), TPB 256/512, cache policies
// (default/.cs/.wt), register budgets — all other axes non-binding.
// Kernel dur 35.2-35.7us == theoretical floor 256MiB/6.05TB/s ~= 35.4us.

#define TPB 256
#define RPT 8

__global__ void __launch_bounds__(TPB)
lagr_ode_kernel(const float4* __restrict__ x,
                const float* __restrict__ k1p,
                const float* __restrict__ k2p,
                float4* __restrict__ out)
{
    const unsigned base = blockIdx.x * (TPB * RPT) + threadIdx.x;
    const float k1 = __ldg(k1p);
    const float k2 = __ldg(k2p);

    // Front-batched independent loads -> 8 LDG.128 in flight per thread
    float4 v[RPT];
#pragma unroll
    for (int j = 0; j < RPT; j++)
        v[j] = __ldcs(&x[base + j * TPB]);

#pragma unroll
    for (int j = 0; j < RPT; j++) {
        const float d = k2 * (v[j].x - v[j].y);   // k2*(q0-q1)
        float4 r;
        r.x = v[j].z;                              // qd0
        r.y = v[j].w;                              // qd1
        r.z = -(k1 * v[j].x + d);                  // qdd0 = -(k1*q0 + k2*(q0-q1))
        r.w = d;                                   // qdd1 =  k2*(q0-q1)
        __stcs(&out[base + j * TPB], r);
    }
}

extern "C" void kernel_launch(void* const* d_in, const int* in_sizes, int n_in,
                              void* d_out, int out_size)
{
    // Inputs (metadata order): t [1], x [B*4], k1 [1], k2 [1]
    const float4* x  = (const float4*)d_in[1];
    const float*  k1 = (const float*)d_in[2];
    const float*  k2 = (const float*)d_in[3];
    float4* out = (float4*)d_out;

    const int rows = in_sizes[1] / 4;              // 8388608
    const int blocks = rows / (TPB * RPT);         // 4096, exact

    lagr_ode_kernel<<<blocks, TPB>>>(x, k1, k2, out);
}

// round 14
// speedup vs baseline: 1.0096x; 1.0096x over previous
#include <cuda_runtime.h>

// lagrangian_ode_func_54640573940227 — FINAL (confirmed optimum, 5 reproductions)
//
// out[i] = { x.z, x.w, -(k1*x0 + k2*(x0-x1)), k2*(x0-x1) }
//
// HBM-roofline streaming kernel. 256 MiB irreducible traffic at ~6.0 TB/s,
// the GB300 mixed read/write DRAM ceiling (75% of 8 TB/s spec).
// 13-round sweep: per-warp MLP 1-16 (optimum 8), occupancy 21-83%, grid
// 1024-32768 (incl. persistent single-wave), TPB 256/512, cache policies
// (default/.cs/.wt), register budgets — all axes beyond MLP depth are
// non-binding. Kernel dur 35.2-35.8us == floor 256MiB/6.05TB/s ~= 35.4us.

#define TPB 256
#define RPT 8

__global__ void __launch_bounds__(TPB)
lagr_ode_kernel(const float4* __restrict__ x,
                const float* __restrict__ k1p,
                const float* __restrict__ k2p,
                float4* __restrict__ out)
{
    const unsigned base = blockIdx.x * (TPB * RPT) + threadIdx.x;
    const float k1 = __ldg(k1p);
    const float k2 = __ldg(k2p);

    // Front-batched independent loads -> 8 LDG.128 in flight per thread
    float4 v[RPT];
#pragma unroll
    for (int j = 0; j < RPT; j++)
        v[j] = __ldcs(&x[base + j * TPB]);

#pragma unroll
    for (int j = 0; j < RPT; j++) {
        const float d = k2 * (v[j].x - v[j].y);   // k2*(q0-q1)
        float4 r;
        r.x = v[j].z;                              // qd0
        r.y = v[j].w;                              // qd1
        r.z = -(k1 * v[j].x + d);                  // qdd0 = -(k1*q0 + k2*(q0-q1))
        r.w = d;                                   // qdd1 =  k2*(q0-q1)
        __stcs(&out[base + j * TPB], r);
    }
}

extern "C" void kernel_launch(void* const* d_in, const int* in_sizes, int n_in,
                              void* d_out, int out_size)
{
    // Inputs (metadata order): t [1], x [B*4], k1 [1], k2 [1]
    const float4* x  = (const float4*)d_in[1];
    const float*  k1 = (const float*)d_in[2];
    const float*  k2 = (const float*)d_in[3];
    float4* out = (float4*)d_out;

    const int rows = in_sizes[1] / 4;              // 8388608
    const int blocks = rows / (TPB * RPT);         // 4096, exact

    lagr_ode_kernel<<<blocks, TPB>>>(x, k1, k2, out);
}